// round 1
// baseline (speedup 1.0000x reference)
#include <cuda_runtime.h>
#include <math.h>

// Problem constants (from reference)
#define BOUND        1.0f
#define MIN_NEAR     0.2f
#define T_THRESH     1e-4f
#define BG_COLOR     1.0f
#define N_STEPS      128
#define CHUNK        32
#define N_CHUNKS     (N_STEPS / CHUNK)

// One warp per ray. Lane l owns sample (chunk*32 + l) within each chunk.
// Exclusive transmittance via warp scan-product; uniform early-exit per chunk.
__global__ __launch_bounds__(256)
void nerf_composite_kernel(const float* __restrict__ rays_o,
                           const float* __restrict__ rays_d,
                           const float* __restrict__ sigmas,
                           const float* __restrict__ rgbs,
                           float* __restrict__ out,
                           int N)
{
    const unsigned FULL = 0xFFFFFFFFu;
    int warp_global = (blockIdx.x * blockDim.x + threadIdx.x) >> 5;
    int lane = threadIdx.x & 31;
    if (warp_global >= N) return;
    const int r = warp_global;

    // ---- near/far slab test (all lanes compute redundantly; loads broadcast) ----
    float ox = rays_o[3 * r + 0], oy = rays_o[3 * r + 1], oz = rays_o[3 * r + 2];
    float dx = rays_d[3 * r + 0], dy = rays_d[3 * r + 1], dz = rays_d[3 * r + 2];
    if (fabsf(dx) < 1e-8f) dx = 1e-8f;
    if (fabsf(dy) < 1e-8f) dy = 1e-8f;
    if (fabsf(dz) < 1e-8f) dz = 1e-8f;

    float ix = 1.0f / dx, iy = 1.0f / dy, iz = 1.0f / dz;
    float t1x = (-BOUND - ox) * ix, t2x = (BOUND - ox) * ix;
    float t1y = (-BOUND - oy) * iy, t2y = (BOUND - oy) * iy;
    float t1z = (-BOUND - oz) * iz, t2z = (BOUND - oz) * iz;

    float nearv = fmaxf(fmaxf(fminf(t1x, t2x), fminf(t1y, t2y)), fminf(t1z, t2z));
    float farv  = fminf(fminf(fmaxf(t1x, t2x), fmaxf(t1y, t2y)), fmaxf(t1z, t2z));
    nearv = fmaxf(nearv, MIN_NEAR);
    farv  = fmaxf(farv, nearv + 1e-4f);

    const float delta = (farv - nearv) * (1.0f / (float)N_STEPS);

    const float* sig_base = sigmas + (size_t)r * N_STEPS;
    const float* rgb_base = rgbs   + (size_t)r * (N_STEPS * 3);

    float T_carry = 1.0f;          // uniform across warp at chunk boundaries
    float wsum = 0.0f, wt = 0.0f;
    float wr = 0.0f, wg = 0.0f, wb = 0.0f;

    #pragma unroll
    for (int c = 0; c < N_CHUNKS; ++c) {
        // Early termination: T exclusive for every remaining sample is <= T_carry,
        // and T_carry <= T_THRESH implies all remaining weights are masked to zero.
        if (T_carry <= T_THRESH) break;

        const int s = c * CHUNK + lane;

        // alpha_i = 1 - exp(-sigma*delta);  v_i = (1 - alpha_i) + 1e-10
        float sigma = sig_base[s];
        float e     = __expf(-sigma * delta);
        float alpha = 1.0f - e;
        float v     = e + 1e-10f;

        // warp inclusive scan-product of v
        float p = v;
        #pragma unroll
        for (int off = 1; off < 32; off <<= 1) {
            float q = __shfl_up_sync(FULL, p, off);
            if (lane >= off) p *= q;
        }
        // exclusive product for this lane
        float excl = __shfl_up_sync(FULL, p, 1);
        if (lane == 0) excl = 1.0f;

        float Ti = T_carry * excl;                        // exclusive transmittance
        float w  = (Ti > T_THRESH) ? alpha * Ti : 0.0f;   // masked weight

        // accumulate
        float tval = nearv + ((float)s + 0.5f) * delta;
        wsum += w;
        wt   += w * tval;

        // rgb loads: lane stride 12B, union 384B contiguous per chunk
        const float* rgb = rgb_base + c * (CHUNK * 3) + 3 * lane;
        wr += w * rgb[0];
        wg += w * rgb[1];
        wb += w * rgb[2];

        // carry full-chunk product forward (lane 31 holds total product)
        T_carry *= __shfl_sync(FULL, p, 31);
    }

    // ---- warp reduction of the 5 accumulators ----
    #pragma unroll
    for (int off = 16; off > 0; off >>= 1) {
        wsum += __shfl_xor_sync(FULL, wsum, off);
        wt   += __shfl_xor_sync(FULL, wt,   off);
        wr   += __shfl_xor_sync(FULL, wr,   off);
        wg   += __shfl_xor_sync(FULL, wg,   off);
        wb   += __shfl_xor_sync(FULL, wb,   off);
    }

    if (lane == 0) {
        float bg = (1.0f - wsum) * BG_COLOR;
        // layout: image [N,3] | depth [N] | depth_normalized [N]
        float* img   = out;
        float* depth = out + (size_t)3 * N;
        float* dnorm = out + (size_t)4 * N;
        img[3 * r + 0] = wr + bg;
        img[3 * r + 1] = wg + bg;
        img[3 * r + 2] = wb + bg;
        depth[r] = wt;
        dnorm[r] = fmaxf(wt - nearv, 0.0f) / (farv - nearv);
    }
}

extern "C" void kernel_launch(void* const* d_in, const int* in_sizes, int n_in,
                              void* d_out, int out_size)
{
    const float* rays_o = (const float*)d_in[0];
    const float* rays_d = (const float*)d_in[1];
    const float* sigmas = (const float*)d_in[2];
    const float* rgbs   = (const float*)d_in[3];
    float* out = (float*)d_out;

    int N = in_sizes[0] / 3;   // rays_o is [N,3]

    // one warp per ray; 8 warps (256 threads) per block
    int warps_per_block = 256 / 32;
    int blocks = (N + warps_per_block - 1) / warps_per_block;
    nerf_composite_kernel<<<blocks, 256>>>(rays_o, rays_d, sigmas, rgbs, out, N);
}

// round 2
// speedup vs baseline: 1.1617x; 1.1617x over previous
#include <cuda_runtime.h>
#include <math.h>

// Problem constants (from reference)
#define BOUND        1.0f
#define MIN_NEAR     0.2f
#define T_THRESH     1e-4f
#define BG_COLOR     1.0f
#define N_STEPS      128
#define CHUNK        32
#define N_CHUNKS     (N_STEPS / CHUNK)

// One warp per ray. Lane l owns sample (chunk*32 + l).
// All 16 loads (4 sigma + 12 rgb) are issued up-front (MLP=16); the four
// per-chunk scan-products run interleaved (ILP=4); cross-chunk transmittance
// coupling is a 3-multiply scalar prefix of the chunk totals.
__global__ __launch_bounds__(256)
void nerf_composite_kernel(const float* __restrict__ rays_o,
                           const float* __restrict__ rays_d,
                           const float* __restrict__ sigmas,
                           const float* __restrict__ rgbs,
                           float* __restrict__ out,
                           int N)
{
    const unsigned FULL = 0xFFFFFFFFu;
    int warp_global = (blockIdx.x * blockDim.x + threadIdx.x) >> 5;
    int lane = threadIdx.x & 31;
    if (warp_global >= N) return;
    const int r = warp_global;

    // ---- batched loads: 4 sigma + 12 rgb LDGs, all independent ----
    const float* sig_base = sigmas + (size_t)r * N_STEPS + lane;
    const float* rgb_base = rgbs   + (size_t)r * (N_STEPS * 3) + 3 * lane;

    float sg[N_CHUNKS];
    float cr[N_CHUNKS], cg[N_CHUNKS], cb[N_CHUNKS];
    #pragma unroll
    for (int c = 0; c < N_CHUNKS; ++c) {
        sg[c] = sig_base[c * CHUNK];
        const float* p = rgb_base + c * (CHUNK * 3);
        cr[c] = p[0];
        cg[c] = p[1];
        cb[c] = p[2];
    }

    // ---- near/far slab test (overlaps with the loads above) ----
    float ox = rays_o[3 * r + 0], oy = rays_o[3 * r + 1], oz = rays_o[3 * r + 2];
    float dx = rays_d[3 * r + 0], dy = rays_d[3 * r + 1], dz = rays_d[3 * r + 2];
    if (fabsf(dx) < 1e-8f) dx = 1e-8f;
    if (fabsf(dy) < 1e-8f) dy = 1e-8f;
    if (fabsf(dz) < 1e-8f) dz = 1e-8f;

    float ix = 1.0f / dx, iy = 1.0f / dy, iz = 1.0f / dz;
    float t1x = (-BOUND - ox) * ix, t2x = (BOUND - ox) * ix;
    float t1y = (-BOUND - oy) * iy, t2y = (BOUND - oy) * iy;
    float t1z = (-BOUND - oz) * iz, t2z = (BOUND - oz) * iz;

    float nearv = fmaxf(fmaxf(fminf(t1x, t2x), fminf(t1y, t2y)), fminf(t1z, t2z));
    float farv  = fminf(fminf(fmaxf(t1x, t2x), fmaxf(t1y, t2y)), fmaxf(t1z, t2z));
    nearv = fmaxf(nearv, MIN_NEAR);
    farv  = fmaxf(farv, nearv + 1e-4f);

    const float delta = (farv - nearv) * (1.0f / (float)N_STEPS);

    // ---- per-chunk alpha / v, then 4 interleaved inclusive scan-products ----
    float alpha[N_CHUNKS], p[N_CHUNKS];
    #pragma unroll
    for (int c = 0; c < N_CHUNKS; ++c) {
        float e = __expf(-sg[c] * delta);
        alpha[c] = 1.0f - e;
        p[c]     = e + 1e-10f;   // v_i = (1 - alpha) + 1e-10
    }

    #pragma unroll
    for (int off = 1; off < 32; off <<= 1) {
        float q0 = __shfl_up_sync(FULL, p[0], off);
        float q1 = __shfl_up_sync(FULL, p[1], off);
        float q2 = __shfl_up_sync(FULL, p[2], off);
        float q3 = __shfl_up_sync(FULL, p[3], off);
        if (lane >= off) {
            p[0] *= q0; p[1] *= q1; p[2] *= q2; p[3] *= q3;
        }
    }

    // exclusive products within each chunk
    float excl[N_CHUNKS];
    #pragma unroll
    for (int c = 0; c < N_CHUNKS; ++c) {
        excl[c] = __shfl_up_sync(FULL, p[c], 1);
        if (lane == 0) excl[c] = 1.0f;
    }

    // scalar (warp-uniform) prefix of chunk totals
    float P0 = __shfl_sync(FULL, p[0], 31);
    float P1 = __shfl_sync(FULL, p[1], 31);
    float P2 = __shfl_sync(FULL, p[2], 31);
    float C[N_CHUNKS];
    C[0] = 1.0f;
    C[1] = P0;
    C[2] = P0 * P1;
    C[3] = C[2] * P2;

    // ---- weights + accumulation ----
    float wsum = 0.0f, wt = 0.0f, wr = 0.0f, wg = 0.0f, wb = 0.0f;
    #pragma unroll
    for (int c = 0; c < N_CHUNKS; ++c) {
        float Ti = C[c] * excl[c];                         // exclusive transmittance
        float w  = (Ti > T_THRESH) ? alpha[c] * Ti : 0.0f; // masked weight
        float tval = nearv + ((float)(c * CHUNK + lane) + 0.5f) * delta;
        wsum += w;
        wt   += w * tval;
        wr   += w * cr[c];
        wg   += w * cg[c];
        wb   += w * cb[c];
    }

    // ---- warp reduction of the 5 accumulators ----
    #pragma unroll
    for (int off = 16; off > 0; off >>= 1) {
        wsum += __shfl_xor_sync(FULL, wsum, off);
        wt   += __shfl_xor_sync(FULL, wt,   off);
        wr   += __shfl_xor_sync(FULL, wr,   off);
        wg   += __shfl_xor_sync(FULL, wg,   off);
        wb   += __shfl_xor_sync(FULL, wb,   off);
    }

    if (lane == 0) {
        float bg = (1.0f - wsum) * BG_COLOR;
        // layout: image [N,3] | depth [N] | depth_normalized [N]
        float* img   = out;
        float* depth = out + (size_t)3 * N;
        float* dnorm = out + (size_t)4 * N;
        img[3 * r + 0] = wr + bg;
        img[3 * r + 1] = wg + bg;
        img[3 * r + 2] = wb + bg;
        depth[r] = wt;
        dnorm[r] = fmaxf(wt - nearv, 0.0f) / (farv - nearv);
    }
}

extern "C" void kernel_launch(void* const* d_in, const int* in_sizes, int n_in,
                              void* d_out, int out_size)
{
    const float* rays_o = (const float*)d_in[0];
    const float* rays_d = (const float*)d_in[1];
    const float* sigmas = (const float*)d_in[2];
    const float* rgbs   = (const float*)d_in[3];
    float* out = (float*)d_out;

    int N = in_sizes[0] / 3;   // rays_o is [N,3]

    int warps_per_block = 256 / 32;
    int blocks = (N + warps_per_block - 1) / warps_per_block;
    nerf_composite_kernel<<<blocks, 256>>>(rays_o, rays_d, sigmas, rgbs, out, N);
}

// round 3
// speedup vs baseline: 1.4109x; 1.2145x over previous
#include <cuda_runtime.h>
#include <math.h>

#define BOUND        1.0f
#define MIN_NEAR     0.2f
#define T_THRESH     1e-4f
#define BG_COLOR     1.0f
#define N_STEPS      128

// One warp per ray. Lane l owns samples 4l..4l+3 (consecutive), so the whole
// ray is covered by 1 float4 sigma load + 3 float4 rgb loads per lane.
// Transmittance: lane-local prefix product (3 mults) + one warp scan-product
// over lane totals (5 shuffle stages) + 1 exclusive shuffle.
__global__ __launch_bounds__(256)
void nerf_composite_kernel(const float* __restrict__ rays_o,
                           const float* __restrict__ rays_d,
                           const float* __restrict__ sigmas,
                           const float* __restrict__ rgbs,
                           float* __restrict__ out,
                           int N)
{
    const unsigned FULL = 0xFFFFFFFFu;
    int warp_global = (blockIdx.x * blockDim.x + threadIdx.x) >> 5;
    int lane = threadIdx.x & 31;
    if (warp_global >= N) return;
    const int r = warp_global;

    // ---- vectorized loads: 4 LDG.128 per lane, all independent ----
    const float4* sig4 = (const float4*)(sigmas + (size_t)r * N_STEPS);
    const float4* rgb4 = (const float4*)(rgbs   + (size_t)r * (N_STEPS * 3));

    float4 s4 = sig4[lane];            // sigmas for samples 4l..4l+3
    float4 c0 = rgb4[3 * lane + 0];    // rgb floats 12l+0 .. 12l+3
    float4 c1 = rgb4[3 * lane + 1];    // rgb floats 12l+4 .. 12l+7
    float4 c2 = rgb4[3 * lane + 2];    // rgb floats 12l+8 .. 12l+11
    // sample 0: (c0.x c0.y c0.z)  sample 1: (c0.w c1.x c1.y)
    // sample 2: (c1.z c1.w c2.x)  sample 3: (c2.y c2.z c2.w)

    // ---- near/far slab test (overlaps the loads) ----
    float ox = rays_o[3 * r + 0], oy = rays_o[3 * r + 1], oz = rays_o[3 * r + 2];
    float dx = rays_d[3 * r + 0], dy = rays_d[3 * r + 1], dz = rays_d[3 * r + 2];
    if (fabsf(dx) < 1e-8f) dx = 1e-8f;
    if (fabsf(dy) < 1e-8f) dy = 1e-8f;
    if (fabsf(dz) < 1e-8f) dz = 1e-8f;

    float ix = 1.0f / dx, iy = 1.0f / dy, iz = 1.0f / dz;
    float t1x = (-BOUND - ox) * ix, t2x = (BOUND - ox) * ix;
    float t1y = (-BOUND - oy) * iy, t2y = (BOUND - oy) * iy;
    float t1z = (-BOUND - oz) * iz, t2z = (BOUND - oz) * iz;

    float nearv = fmaxf(fmaxf(fminf(t1x, t2x), fminf(t1y, t2y)), fminf(t1z, t2z));
    float farv  = fminf(fminf(fmaxf(t1x, t2x), fmaxf(t1y, t2y)), fmaxf(t1z, t2z));
    nearv = fmaxf(nearv, MIN_NEAR);
    farv  = fmaxf(farv, nearv + 1e-4f);

    const float delta = (farv - nearv) * (1.0f / (float)N_STEPS);

    // ---- per-sample alpha & survival v ----
    float e0 = __expf(-s4.x * delta);
    float e1 = __expf(-s4.y * delta);
    float e2 = __expf(-s4.z * delta);
    float e3 = __expf(-s4.w * delta);
    float a0 = 1.0f - e0, a1 = 1.0f - e1, a2 = 1.0f - e2, a3 = 1.0f - e3;
    float v0 = e0 + 1e-10f, v1 = e1 + 1e-10f, v2 = e2 + 1e-10f, v3 = e3 + 1e-10f;

    // lane-local prefix products
    float lp1 = v0;
    float lp2 = v0 * v1;
    float lp3 = lp2 * v2;
    float tot = lp3 * v3;

    // warp inclusive scan-product over lane totals
    float p = tot;
    #pragma unroll
    for (int off = 1; off < 32; off <<= 1) {
        float q = __shfl_up_sync(FULL, p, off);
        if (lane >= off) p *= q;
    }
    float excl = __shfl_up_sync(FULL, p, 1);
    if (lane == 0) excl = 1.0f;

    // exclusive transmittance per sample
    float T0 = excl;
    float T1 = excl * lp1;
    float T2 = excl * lp2;
    float T3 = excl * lp3;

    float w0 = (T0 > T_THRESH) ? a0 * T0 : 0.0f;
    float w1 = (T1 > T_THRESH) ? a1 * T1 : 0.0f;
    float w2 = (T2 > T_THRESH) ? a2 * T2 : 0.0f;
    float w3 = (T3 > T_THRESH) ? a3 * T3 : 0.0f;

    // ---- accumulate ----
    float tbase = nearv + ((float)(4 * lane) + 0.5f) * delta;
    float wsum = w0 + w1 + w2 + w3;
    float wt = w0 * tbase
             + w1 * (tbase + delta)
             + w2 * (tbase + 2.0f * delta)
             + w3 * (tbase + 3.0f * delta);
    float wr = w0 * c0.x + w1 * c0.w + w2 * c1.z + w3 * c2.y;
    float wg = w0 * c0.y + w1 * c1.x + w2 * c1.w + w3 * c2.z;
    float wb = w0 * c0.z + w1 * c1.y + w2 * c2.x + w3 * c2.w;

    // ---- warp reduction of the 5 accumulators ----
    #pragma unroll
    for (int off = 16; off > 0; off >>= 1) {
        wsum += __shfl_xor_sync(FULL, wsum, off);
        wt   += __shfl_xor_sync(FULL, wt,   off);
        wr   += __shfl_xor_sync(FULL, wr,   off);
        wg   += __shfl_xor_sync(FULL, wg,   off);
        wb   += __shfl_xor_sync(FULL, wb,   off);
    }

    if (lane == 0) {
        float bg = (1.0f - wsum) * BG_COLOR;
        float* img   = out;
        float* depth = out + (size_t)3 * N;
        float* dnorm = out + (size_t)4 * N;
        img[3 * r + 0] = wr + bg;
        img[3 * r + 1] = wg + bg;
        img[3 * r + 2] = wb + bg;
        depth[r] = wt;
        dnorm[r] = fmaxf(wt - nearv, 0.0f) / (farv - nearv);
    }
}

extern "C" void kernel_launch(void* const* d_in, const int* in_sizes, int n_in,
                              void* d_out, int out_size)
{
    const float* rays_o = (const float*)d_in[0];
    const float* rays_d = (const float*)d_in[1];
    const float* sigmas = (const float*)d_in[2];
    const float* rgbs   = (const float*)d_in[3];
    float* out = (float*)d_out;

    int N = in_sizes[0] / 3;   // rays_o is [N,3]

    int warps_per_block = 256 / 32;
    int blocks = (N + warps_per_block - 1) / warps_per_block;
    nerf_composite_kernel<<<blocks, 256>>>(rays_o, rays_d, sigmas, rgbs, out, N);
}